// round 10
// baseline (speedup 1.0000x reference)
#include <cuda_runtime.h>
#include <math.h>
#include <stdint.h>

#define NN 20000
#define NE 640000
#define DD 128
#define OUTD 256
#define BBATCH 64
#define HOUT 62
#define MPI (HOUT*HOUT)   // 3844 pixels per image
#define MT 31             // M-tiles of 128 per image
#define KTOT 1152
#define KC 16             // K chunk
#define NCHUNK (KTOT/KC)  // 72
#define ASTRIDE 20        // padded floats per row (80B, 16B-aligned, ldmatrix conflict-free)
#define BUFF (128*ASTRIDE)  // floats per A or B region per stage

// ---------------- scratch ----------------
__device__ __align__(16) float g_inv_sigma[4];
__device__ __align__(16) float g_ws[DD * KTOT];        // conv weights [cout][k]/sigma, tf32-rna
__device__ __align__(16) float g_fcvT[512 * OUTD];
__device__ __align__(16) float g_fctT[DD * OUTD];
__device__ __align__(16) float g_partial[BBATCH * MT * 4 * DD];
__device__ __align__(16) float g_pool_vis[BBATCH * DD * 4];
__device__ __align__(16) float g_topo_part[BBATCH * 4 * DD];
__device__ __align__(16) float g_deg[NN];
__device__ __align__(16) float g_dis[NN];
__device__ __align__(16) float g_xw[NN * DD];
__device__ __align__(16) float g_h[NN * DD];

__device__ __forceinline__ int clampi(int v, int lo, int hi) {
    return v < lo ? lo : (v > hi ? hi : v);
}
__device__ __forceinline__ uint32_t f2tf32(float f) {
    uint32_t u;
    asm("cvt.rna.tf32.f32 %0, %1;" : "=r"(u) : "f"(f));
    return u;
}
__device__ __forceinline__ uint32_t smem_u32(const void* p) {
    uint32_t a;
    asm("{ .reg .u64 t; cvta.to.shared.u64 t, %1; cvt.u32.u64 %0, t; }" : "=r"(a) : "l"(p));
    return a;
}
__device__ __forceinline__ void mma_tf32(float* d, const uint32_t* a, const uint32_t* b) {
    asm volatile(
        "mma.sync.aligned.m16n8k8.row.col.f32.tf32.tf32.f32 "
        "{%0,%1,%2,%3}, {%4,%5,%6,%7}, {%8,%9}, {%0,%1,%2,%3};"
        : "+f"(d[0]), "+f"(d[1]), "+f"(d[2]), "+f"(d[3])
        : "r"(a[0]), "r"(a[1]), "r"(a[2]), "r"(a[3]), "r"(b[0]), "r"(b[1]));
}
__device__ __forceinline__ void ldsm_x4(uint32_t* r, uint32_t addr) {
    asm volatile("ldmatrix.sync.aligned.m8n8.x4.shared.b16 {%0,%1,%2,%3}, [%4];"
                 : "=r"(r[0]), "=r"(r[1]), "=r"(r[2]), "=r"(r[3]) : "r"(addr));
}
__device__ __forceinline__ void cp_async4(uint32_t dst, const void* src, int zfill) {
    asm volatile("cp.async.ca.shared.global [%0], [%1], 4, %2;"
                 :: "r"(dst), "l"(src), "r"(zfill) : "memory");
}
__device__ __forceinline__ void cp_async16(uint32_t dst, const void* src) {
    asm volatile("cp.async.cg.shared.global [%0], [%1], 16;"
                 :: "r"(dst), "l"(src) : "memory");
}

// ---------------- reductions ----------------
__device__ __forceinline__ float block_reduce_sum(float v, float* red) {
    int tid = threadIdx.x;
    red[tid] = v;
    __syncthreads();
    for (int s = 128; s > 0; s >>= 1) {
        if (tid < s) red[tid] += red[tid + s];
        __syncthreads();
    }
    float r = red[0];
    __syncthreads();
    return r;
}

// ---------------- spectral norm sigma ----------------
__global__ void sigma_kernel(const float* W, const float* u, int R, int C, int slot) {
    __shared__ float sv[1152];
    __shared__ float red[256];
    int tid = threadIdx.x;

    float ss = 0.f;
    for (int j = tid; j < C; j += 256) {
        float t = 0.f;
        for (int i = 0; i < R; i++) t += W[i * C + j] * u[i];
        sv[j] = t;
        ss += t * t;
    }
    __syncthreads();
    float nrm2 = block_reduce_sum(ss, red);
    float invn = 1.0f / (sqrtf(nrm2) + 1e-12f);

    float ss2 = 0.f;
    for (int i = tid; i < R; i += 256) {
        float s = 0.f;
        for (int j = 0; j < C; j++) s += W[i * C + j] * sv[j];
        s *= invn;
        ss2 += s * s;
    }
    float sig2 = block_reduce_sum(ss2, red);
    if (tid == 0) {
        float sigma = sig2 / (sqrtf(sig2) + 1e-12f);
        g_inv_sigma[slot] = 1.0f / sigma;
    }
}

// ---------------- scale / transpose weights ----------------
__global__ void scale_w(const float* src) {      // conv_w [cout][k], pre-round to tf32
    int idx = blockIdx.x * 256 + threadIdx.x;
    if (idx < 128 * 1152) g_ws[idx] = __uint_as_float(f2tf32(src[idx] * g_inv_sigma[0]));
}
__global__ void transpose_fcv(const float* src) {
    int idx = blockIdx.x * 256 + threadIdx.x;
    if (idx >= 256 * 512) return;
    int r = idx / 512, c = idx - r * 512;
    g_fcvT[c * 256 + r] = src[idx] * g_inv_sigma[1];
}
__global__ void transpose_fct(const float* src) {
    int idx = blockIdx.x * 256 + threadIdx.x;
    if (idx >= 256 * 128) return;
    int r = idx / 128, c = idx - r * 128;
    g_fctT[c * 256 + r] = src[idx] * g_inv_sigma[2];
}

// ---------------- init ----------------
__global__ void init_kernel() {
    int idx = blockIdx.x * 256 + threadIdx.x;
    if (idx < NN * DD) g_h[idx] = 0.f;
    if (idx < NN) g_deg[idx] = 1.0f;
}

// ---------------- degree + normalization ----------------
__global__ void deg_kernel(const int* __restrict__ ei) {
    int e = blockIdx.x * 256 + threadIdx.x;
    if (e < NE) atomicAdd(&g_deg[clampi(ei[NE + e], 0, NN - 1)], 1.0f);
}
__global__ void dis_kernel() {
    int i = blockIdx.x * 256 + threadIdx.x;
    if (i < NN) g_dis[i] = rsqrtf(g_deg[i]);
}

// ---------------- xw = topo @ gcn_w ----------------
__global__ void xw_kernel(const float* __restrict__ topo, const float* __restrict__ gw) {
    __shared__ float st[8 * 128];
    int n0 = blockIdx.x * 8;
    int tid = threadIdx.x;
#pragma unroll
    for (int i = 0; i < 8; i++) st[i * 128 + tid] = topo[(n0 + i) * 128 + tid];
    __syncthreads();
    float acc[8];
#pragma unroll
    for (int r = 0; r < 8; r++) acc[r] = 0.f;
    for (int k = 0; k < 128; k++) {
        float w = gw[k * 128 + tid];
#pragma unroll
        for (int r = 0; r < 8; r++) acc[r] += st[r * 128 + k] * w;
    }
#pragma unroll
    for (int r = 0; r < 8; r++) g_xw[(n0 + r) * 128 + tid] = acc[r];
}

// ---------------- edge scatter via red.v4 ----------------
__global__ void scatter_kernel(const int* __restrict__ ei) {
    int e = blockIdx.x * 8 + (threadIdx.x >> 5);
    if (e >= NE) return;
    int lane = threadIdx.x & 31;
    int src = clampi(ei[e], 0, NN - 1);
    int dst = clampi(ei[NE + e], 0, NN - 1);
    float nrm = g_dis[src] * g_dis[dst];
    float4 v = *(const float4*)&g_xw[src * 128 + lane * 4];
    asm volatile("red.global.add.v4.f32 [%0], {%1, %2, %3, %4};"
                 :: "l"(&g_h[dst * 128 + lane * 4]),
                    "f"(v.x * nrm), "f"(v.y * nrm), "f"(v.z * nrm), "f"(v.w * nrm)
                 : "memory");
}

// ---------------- topo pool ----------------
__global__ void topo_pool_kernel(const int* __restrict__ batch, const float* __restrict__ gb) {
    int b = blockIdx.x;
    int stripe = blockIdx.y;
    int c = threadIdx.x;

    int lo = 0, hi = NN;
    while (lo < hi) { int mid = (lo + hi) >> 1; if (batch[mid] < b) lo = mid + 1; else hi = mid; }
    int s = lo;
    lo = s; hi = NN;
    while (lo < hi) { int mid = (lo + hi) >> 1; if (batch[mid] < b + 1) lo = mid + 1; else hi = mid; }
    int e = lo;

    float bias = gb[c];
    float m = -INFINITY;
    for (int n = s + stripe; n < e; n += 4) {
        float d = g_dis[n];
        float val = g_h[n * 128 + c] + d * d * g_xw[n * 128 + c] + bias;
        val = (val >= 0.f) ? val : 0.2f * val;
        m = fmaxf(m, val);
    }
    g_topo_part[(b * 4 + stripe) * 128 + c] = m;
}

// ---------------- conv3x3: tf32 mma + cp.async + ldmatrix, double-buffered ----------
// block 128 pixels x 128 cout; 8 warps 4x2 (warp tile 32x64)
__global__ void __launch_bounds__(256, 2)
conv_mma_kernel(const float* __restrict__ vis, const float* __restrict__ cb) {
    // sbuf[stage] = [ A: 128 x ASTRIDE | B: 128 x ASTRIDE ]
    __shared__ __align__(16) float sbuf[2][2 * BUFF];
    __shared__ int skoff[KTOT];
    __shared__ float sbias[DD];
    __shared__ unsigned char srowreg[128];

    int tid = threadIdx.x;
    int warp = tid >> 5, lane = tid & 31;
    int wm = warp & 3;        // rows 32*wm
    int wn = warp >> 2;       // cols 64*wn
    int gq = lane >> 2, tg = lane & 3;

    int img = blockIdx.x / MT;
    int mt = blockIdx.x - img * MT;
    int m0 = mt * 128;

    for (int k = tid; k < KTOT; k += 256) {
        int ci = k / 9, rem = k - ci * 9, ky = rem / 3, kx = rem - ky * 3;
        skoff[k] = ci * 4096 + ky * 64 + kx;
    }
    if (tid < 128) {
        sbias[tid] = cb[tid];
        int s = m0 + tid;
        unsigned char r = 4;
        if (s < MPI) {
            int yy = s / HOUT, xx = s - yy * HOUT;
            r = (unsigned char)(((yy >= 31) ? 2 : 0) + ((xx >= 31) ? 1 : 0));
        }
        srowreg[tid] = r;
    }

    // A gather: pixel p = tid&127, ks kb..kb+7 (kb = (tid>>7)*8)
    int p = tid & 127;
    int kb = (tid >> 7) * 8;
    int s = m0 + p;
    bool valid = (s < MPI);
    int y = valid ? (s / HOUT) : 0;
    int x = valid ? (s - y * HOUT) : 0;
    const float* base = vis + (size_t)img * 128 * 4096 + y * 64 + x;
    int zf = valid ? 4 : 0;

    // B: cout bn = tid>>1, k half bkh = (tid&1)*8
    int bn = tid >> 1;
    int bkh = (tid & 1) * 8;
    const float* wrow = &g_ws[bn * KTOT + bkh];

    uint32_t sb0 = smem_u32(sbuf);
    uint32_t aDst = sb0 + ((p * ASTRIDE + kb) << 2);
    uint32_t bDst = sb0 + (BUFF << 2) + ((bn * ASTRIDE + bkh) << 2);
    const uint32_t stageBytes = 2 * BUFF * 4;

    // ldmatrix lane offsets
    int mR = lane >> 3, rr = lane & 7;
    uint32_t offA[2], offB[4];
#pragma unroll
    for (int mi = 0; mi < 2; mi++)
        offA[mi] = (((wm * 32 + mi * 16 + (mR & 1) * 8 + rr) * ASTRIDE + (mR >> 1) * 4) << 2);
#pragma unroll
    for (int pr = 0; pr < 4; pr++)
        offB[pr] = (BUFF << 2) + (((wn * 64 + pr * 16 + (mR >> 1) * 8 + rr) * ASTRIDE + (mR & 1) * 4) << 2);

    float acc[2][8][4];
#pragma unroll
    for (int mi = 0; mi < 2; mi++)
#pragma unroll
        for (int ni = 0; ni < 8; ni++)
#pragma unroll
            for (int c = 0; c < 4; c++) acc[mi][ni][c] = 0.f;

    __syncthreads();   // tables ready

    // prologue: issue chunk 0 into stage 0
    {
        const int kg0 = 0;
#pragma unroll
        for (int i = 0; i < 8; i++)
            cp_async4(aDst + (i << 2), base + skoff[kg0 + kb + i], zf);
        cp_async16(bDst, wrow + kg0);
        cp_async16(bDst + 16, wrow + kg0 + 4);
        asm volatile("cp.async.commit_group;" ::: "memory");
    }

    for (int ch = 0; ch < NCHUNK; ch++) {
        if (ch + 1 < NCHUNK) {
            int kg0 = (ch + 1) * KC;
            uint32_t st = ((ch + 1) & 1) * stageBytes;
#pragma unroll
            for (int i = 0; i < 8; i++)
                cp_async4(aDst + st + (i << 2), base + skoff[kg0 + kb + i], zf);
            cp_async16(bDst + st, wrow + kg0);
            cp_async16(bDst + st + 16, wrow + kg0 + 4);
            asm volatile("cp.async.commit_group;" ::: "memory");
            asm volatile("cp.async.wait_group 1;" ::: "memory");
        } else {
            asm volatile("cp.async.wait_group 0;" ::: "memory");
        }
        __syncthreads();   // stage ch data visible

        uint32_t st = (ch & 1) * stageBytes;
#pragma unroll
        for (int ks = 0; ks < 2; ks++) {
            uint32_t kofs = st + ks * 32;
            uint32_t a[2][4], b[4][4];
#pragma unroll
            for (int mi = 0; mi < 2; mi++) ldsm_x4(a[mi], sb0 + offA[mi] + kofs);
#pragma unroll
            for (int pr = 0; pr < 4; pr++) ldsm_x4(b[pr], sb0 + offB[pr] + kofs);
#pragma unroll
            for (int mi = 0; mi < 2; mi++)
#pragma unroll
                for (int pr = 0; pr < 4; pr++) {
                    mma_tf32(acc[mi][pr * 2 + 0], a[mi], &b[pr][0]);
                    mma_tf32(acc[mi][pr * 2 + 1], a[mi], &b[pr][2]);
                }
        }
        __syncthreads();   // all reads of stage ch done before it is overwritten
    }

    // ---------------- epilogue: 4 column passes of 32 cols ----------------
    float* sm = sbuf[0];   // overlay [128][33] = 4224 floats <= 2*BUFF
    for (int q = 0; q < 4; q++) {
        if ((q >> 1) == wn) {
            int ni0 = (q & 1) * 4;
#pragma unroll
            for (int mi = 0; mi < 2; mi++) {
#pragma unroll
                for (int nj = 0; nj < 4; nj++) {
                    int ni = ni0 + nj;
                    int colg = wn * 64 + ni * 8 + 2 * tg;
                    int colp = (colg - q * 32);
                    int r0 = wm * 32 + mi * 16 + gq;
#pragma unroll
                    for (int cc = 0; cc < 2; cc++) {
                        float v0 = acc[mi][ni][cc] + sbias[colg + cc];
                        v0 = (v0 >= 0.f) ? v0 : 0.2f * v0;
                        float v2 = acc[mi][ni][2 + cc] + sbias[colg + cc];
                        v2 = (v2 >= 0.f) ? v2 : 0.2f * v2;
                        sm[r0 * 33 + colp + cc] = v0;
                        sm[(r0 + 8) * 33 + colp + cc] = v2;
                    }
                }
            }
        }
        __syncthreads();
        if (tid < 128) {
            int ccol = tid & 31;
            int myreg = tid >> 5;
            float mx = -INFINITY;
            for (int row = 0; row < 128; row++) {
                float v = sm[row * 33 + ccol];
                mx = (srowreg[row] == (unsigned char)myreg) ? fmaxf(mx, v) : mx;
            }
            g_partial[((img * MT + mt) * 4 + myreg) * 128 + q * 32 + ccol] = mx;
        }
        __syncthreads();
    }
}

// ---------------- reduce conv-tile partials -> g_pool_vis ----------------
__global__ void vis_reduce_kernel() {
    int img = blockIdx.x;
    int o = threadIdx.x;    // 512
    int r = o >> 7;
    int col = o & 127;
    float m = -INFINITY;
    for (int mt = 0; mt < MT; mt++)
        m = fmaxf(m, g_partial[((img * MT + mt) * 4 + r) * 128 + col]);
    g_pool_vis[img * 512 + col * 4 + r] = m;
}

// ---------------- vis score ----------------
__global__ void vis_score_kernel(const float* __restrict__ fcvb, float* __restrict__ out) {
    __shared__ float xs[512];
    int b = blockIdx.x, tid = threadIdx.x;
    for (int i = tid; i < 512; i += 256) xs[i] = g_pool_vis[b * 512 + i];
    __syncthreads();
    float acc = fcvb[tid];
    for (int j = 0; j < 512; j++) acc += xs[j] * g_fcvT[j * OUTD + tid];
    out[b * OUTD + tid] = acc;
}

// ---------------- topo score ----------------
__global__ void topo_score_kernel(const float* __restrict__ fctb, float* __restrict__ out) {
    __shared__ float xs[128];
    int b = blockIdx.x, tid = threadIdx.x;
    if (tid < 128) {
        float m = g_topo_part[(b * 4 + 0) * 128 + tid];
        m = fmaxf(m, g_topo_part[(b * 4 + 1) * 128 + tid]);
        m = fmaxf(m, g_topo_part[(b * 4 + 2) * 128 + tid]);
        m = fmaxf(m, g_topo_part[(b * 4 + 3) * 128 + tid]);
        xs[tid] = m;
    }
    __syncthreads();
    float acc = fctb[tid];
    for (int j = 0; j < 128; j++) acc += xs[j] * g_fctT[j * OUTD + tid];
    out[BBATCH * OUTD + b * OUTD + tid] = acc;
}

// ---------------- launch (conv placed 4th: ncu -s5-c1 lands there) ----------------
extern "C" void kernel_launch(void* const* d_in, const int* in_sizes, int n_in,
                              void* d_out, int out_size) {
    const float* vis    = (const float*)d_in[0];
    const float* topo   = (const float*)d_in[1];
    const int*   ei     = (const int*)d_in[2];
    const int*   batch  = (const int*)d_in[3];
    const float* conv_w = (const float*)d_in[4];
    const float* conv_b = (const float*)d_in[5];
    const float* conv_u = (const float*)d_in[6];
    const float* fcv_w  = (const float*)d_in[7];
    const float* fcv_b  = (const float*)d_in[8];
    const float* fcv_u  = (const float*)d_in[9];
    const float* gcn_w  = (const float*)d_in[10];
    const float* gcn_b  = (const float*)d_in[11];
    const float* fct_w  = (const float*)d_in[12];
    const float* fct_b  = (const float*)d_in[13];
    const float* fct_u  = (const float*)d_in[14];
    float*       out    = (float*)d_out;

    // 1..3
    sigma_kernel<<<1, 256>>>(conv_w, conv_u, 128, 1152, 0);
    scale_w<<<(128 * 1152 + 255) / 256, 256>>>(conv_w);
    init_kernel<<<(NN * DD + 255) / 256, 256>>>();
    // 4: conv (profiled slot)
    conv_mma_kernel<<<BBATCH * MT, 256>>>(vis, conv_b);

    // topo head
    deg_kernel<<<(NE + 255) / 256, 256>>>(ei);
    dis_kernel<<<(NN + 255) / 256, 256>>>();
    xw_kernel<<<NN / 8, 128>>>(topo, gcn_w);
    scatter_kernel<<<NE / 8, 256>>>(ei);

    // remaining weight prep
    sigma_kernel<<<1, 256>>>(fcv_w, fcv_u, 256, 512, 1);
    sigma_kernel<<<1, 256>>>(fct_w, fct_u, 256, 128, 2);
    transpose_fcv<<<(256 * 512 + 255) / 256, 256>>>(fcv_w);
    transpose_fct<<<(256 * 128 + 255) / 256, 256>>>(fct_w);

    vis_reduce_kernel<<<BBATCH, 512>>>();
    {
        dim3 g(BBATCH, 4);
        topo_pool_kernel<<<g, 128>>>(batch, gcn_b);
    }

    vis_score_kernel<<<BBATCH, 256>>>(fcv_b, out);
    topo_score_kernel<<<BBATCH, 256>>>(fct_b, out);
}

// round 11
// speedup vs baseline: 2.0487x; 2.0487x over previous
#include <cuda_runtime.h>
#include <math.h>
#include <stdint.h>

#define NN 20000
#define NE 640000
#define DD 128
#define OUTD 256
#define BBATCH 64
#define HOUT 62
#define MPI (HOUT*HOUT)   // 3844 pixels per image
#define MT 31             // M-tiles of 128 per image
#define KTOT 1152
#define KC 16             // K chunk
#define NCHUNK (KTOT/KC)  // 72
#define ASTRIDE 20        // floats per row (80B): conflict-free for STS.128 + ldmatrix
#define BUFF (128*ASTRIDE)  // floats per A (or B) region per stage

// ---------------- scratch ----------------
__device__ __align__(16) float g_inv_sigma[4];
__device__ __align__(16) float g_wsp[NCHUNK * BUFF];   // weight panels [ch][row][ASTRIDE], tf32
__device__ __align__(16) float g_fcvT[512 * OUTD];
__device__ __align__(16) float g_fctT[DD * OUTD];
__device__ __align__(16) float g_partial[BBATCH * MT * 4 * DD];
__device__ __align__(16) float g_pool_vis[BBATCH * DD * 4];
__device__ __align__(16) float g_topo_part[BBATCH * 4 * DD];
__device__ __align__(16) float g_deg[NN];
__device__ __align__(16) float g_dis[NN];
__device__ __align__(16) float g_xw[NN * DD];
__device__ __align__(16) float g_h[NN * DD];

__device__ __forceinline__ int clampi(int v, int lo, int hi) {
    return v < lo ? lo : (v > hi ? hi : v);
}
__device__ __forceinline__ uint32_t f2tf32(float f) {
    uint32_t u;
    asm("cvt.rna.tf32.f32 %0, %1;" : "=r"(u) : "f"(f));
    return u;
}
__device__ __forceinline__ uint32_t smem_u32(const void* p) {
    uint32_t a;
    asm("{ .reg .u64 t; cvta.to.shared.u64 t, %1; cvt.u32.u64 %0, t; }" : "=r"(a) : "l"(p));
    return a;
}
__device__ __forceinline__ void mma_tf32(float* d, const uint32_t* a, const uint32_t* b) {
    asm volatile(
        "mma.sync.aligned.m16n8k8.row.col.f32.tf32.tf32.f32 "
        "{%0,%1,%2,%3}, {%4,%5,%6,%7}, {%8,%9}, {%0,%1,%2,%3};"
        : "+f"(d[0]), "+f"(d[1]), "+f"(d[2]), "+f"(d[3])
        : "r"(a[0]), "r"(a[1]), "r"(a[2]), "r"(a[3]), "r"(b[0]), "r"(b[1]));
}
__device__ __forceinline__ void ldsm_x4(uint32_t* r, uint32_t addr) {
    asm volatile("ldmatrix.sync.aligned.m8n8.x4.shared.b16 {%0,%1,%2,%3}, [%4];"
                 : "=r"(r[0]), "=r"(r[1]), "=r"(r[2]), "=r"(r[3]) : "r"(addr));
}

// ---------------- reductions ----------------
__device__ __forceinline__ float block_reduce_sum(float v, float* red) {
    int tid = threadIdx.x;
    red[tid] = v;
    __syncthreads();
    for (int s = 128; s > 0; s >>= 1) {
        if (tid < s) red[tid] += red[tid + s];
        __syncthreads();
    }
    float r = red[0];
    __syncthreads();
    return r;
}

// ---------------- spectral norm sigma ----------------
__global__ void sigma_kernel(const float* W, const float* u, int R, int C, int slot) {
    __shared__ float sv[1152];
    __shared__ float red[256];
    int tid = threadIdx.x;

    float ss = 0.f;
    for (int j = tid; j < C; j += 256) {
        float t = 0.f;
        for (int i = 0; i < R; i++) t += W[i * C + j] * u[i];
        sv[j] = t;
        ss += t * t;
    }
    __syncthreads();
    float nrm2 = block_reduce_sum(ss, red);
    float invn = 1.0f / (sqrtf(nrm2) + 1e-12f);

    float ss2 = 0.f;
    for (int i = tid; i < R; i += 256) {
        float s = 0.f;
        for (int j = 0; j < C; j++) s += W[i * C + j] * sv[j];
        s *= invn;
        ss2 += s * s;
    }
    float sig2 = block_reduce_sum(ss2, red);
    if (tid == 0) {
        float sigma = sig2 / (sqrtf(sig2) + 1e-12f);
        g_inv_sigma[slot] = 1.0f / sigma;
    }
}

// ---------------- weight prep: scale, tf32-round, lay out in smem-panel order ------
__global__ void scale_w(const float* src) {      // src [cout][k] -> g_wsp[ch][cout][20]
    int idx = blockIdx.x * 256 + threadIdx.x;
    if (idx >= 128 * 1152) return;
    int r = idx / 1152, k = idx - r * 1152;
    int ch = k >> 4, kk = k & 15;
    g_wsp[ch * BUFF + r * ASTRIDE + kk] = __uint_as_float(f2tf32(src[idx] * g_inv_sigma[0]));
}
__global__ void transpose_fcv(const float* src) {
    int idx = blockIdx.x * 256 + threadIdx.x;
    if (idx >= 256 * 512) return;
    int r = idx / 512, c = idx - r * 512;
    g_fcvT[c * 256 + r] = src[idx] * g_inv_sigma[1];
}
__global__ void transpose_fct(const float* src) {
    int idx = blockIdx.x * 256 + threadIdx.x;
    if (idx >= 256 * 128) return;
    int r = idx / 128, c = idx - r * 128;
    g_fctT[c * 256 + r] = src[idx] * g_inv_sigma[2];
}

// ---------------- init ----------------
__global__ void init_kernel() {
    int idx = blockIdx.x * 256 + threadIdx.x;
    if (idx < NN * DD) g_h[idx] = 0.f;
    if (idx < NN) g_deg[idx] = 1.0f;
}

// ---------------- degree + normalization ----------------
__global__ void deg_kernel(const int* __restrict__ ei) {
    int e = blockIdx.x * 256 + threadIdx.x;
    if (e < NE) atomicAdd(&g_deg[clampi(ei[NE + e], 0, NN - 1)], 1.0f);
}
__global__ void dis_kernel() {
    int i = blockIdx.x * 256 + threadIdx.x;
    if (i < NN) g_dis[i] = rsqrtf(g_deg[i]);
}

// ---------------- xw = topo @ gcn_w ----------------
__global__ void xw_kernel(const float* __restrict__ topo, const float* __restrict__ gw) {
    __shared__ float st[8 * 128];
    int n0 = blockIdx.x * 8;
    int tid = threadIdx.x;
#pragma unroll
    for (int i = 0; i < 8; i++) st[i * 128 + tid] = topo[(n0 + i) * 128 + tid];
    __syncthreads();
    float acc[8];
#pragma unroll
    for (int r = 0; r < 8; r++) acc[r] = 0.f;
    for (int k = 0; k < 128; k++) {
        float w = gw[k * 128 + tid];
#pragma unroll
        for (int r = 0; r < 8; r++) acc[r] += st[r * 128 + k] * w;
    }
#pragma unroll
    for (int r = 0; r < 8; r++) g_xw[(n0 + r) * 128 + tid] = acc[r];
}

// ---------------- edge scatter via red.v4 ----------------
__global__ void scatter_kernel(const int* __restrict__ ei) {
    int e = blockIdx.x * 8 + (threadIdx.x >> 5);
    if (e >= NE) return;
    int lane = threadIdx.x & 31;
    int src = clampi(ei[e], 0, NN - 1);
    int dst = clampi(ei[NE + e], 0, NN - 1);
    float nrm = g_dis[src] * g_dis[dst];
    float4 v = *(const float4*)&g_xw[src * 128 + lane * 4];
    asm volatile("red.global.add.v4.f32 [%0], {%1, %2, %3, %4};"
                 :: "l"(&g_h[dst * 128 + lane * 4]),
                    "f"(v.x * nrm), "f"(v.y * nrm), "f"(v.z * nrm), "f"(v.w * nrm)
                 : "memory");
}

// ---------------- topo pool ----------------
__global__ void topo_pool_kernel(const int* __restrict__ batch, const float* __restrict__ gb) {
    int b = blockIdx.x;
    int stripe = blockIdx.y;
    int c = threadIdx.x;

    int lo = 0, hi = NN;
    while (lo < hi) { int mid = (lo + hi) >> 1; if (batch[mid] < b) lo = mid + 1; else hi = mid; }
    int s = lo;
    lo = s; hi = NN;
    while (lo < hi) { int mid = (lo + hi) >> 1; if (batch[mid] < b + 1) lo = mid + 1; else hi = mid; }
    int e = lo;

    float bias = gb[c];
    float m = -INFINITY;
    for (int n = s + stripe; n < e; n += 4) {
        float d = g_dis[n];
        float val = g_h[n * 128 + c] + d * d * g_xw[n * 128 + c] + bias;
        val = (val >= 0.f) ? val : 0.2f * val;
        m = fmaxf(m, val);
    }
    g_topo_part[(b * 4 + stripe) * 128 + c] = m;
}

// ---------------- conv3x3: tf32 mma + ldmatrix, conflict-free STS.128 fills --------
// block 128 pixels x 128 cout; 8 warps 4x2 (warp tile 32x64)
__global__ void __launch_bounds__(256, 2)
conv_mma_kernel(const float* __restrict__ vis, const float* __restrict__ cb) {
    __shared__ __align__(16) float sbuf[2][2 * BUFF];   // stage: A(BUFF) | B(BUFF)
    __shared__ int skoff[KTOT];
    __shared__ float sbias[DD];
    __shared__ unsigned char srowreg[128];

    int tid = threadIdx.x;
    int warp = tid >> 5, lane = tid & 31;
    int wm = warp & 3;        // rows 32*wm
    int wn = warp >> 2;       // cols 64*wn
    int gq = lane >> 2, tg = lane & 3;

    int img = blockIdx.x / MT;
    int mt = blockIdx.x - img * MT;
    int m0 = mt * 128;

    for (int k = tid; k < KTOT; k += 256) {
        int ci = k / 9, rem = k - ci * 9, ky = rem / 3, kx = rem - ky * 3;
        skoff[k] = ci * 4096 + ky * 64 + kx;
    }
    if (tid < 128) {
        sbias[tid] = cb[tid];
        int s = m0 + tid;
        unsigned char r = 4;
        if (s < MPI) {
            int yy = s / HOUT, xx = s - yy * HOUT;
            r = (unsigned char)(((yy >= 31) ? 2 : 0) + ((xx >= 31) ? 1 : 0));
        }
        srowreg[tid] = r;
    }

    // A gather: pixel p = tid&127, k sub-range kb..kb+7 (kb = (tid>>7)*8)
    int p = tid & 127;
    int kb = (tid >> 7) * 8;
    int s = m0 + p;
    bool valid = (s < MPI);
    int y = valid ? (s / HOUT) : 0;
    int x = valid ? (s - y * HOUT) : 0;
    const float* base = vis + (size_t)img * 128 * 4096 + y * 64 + x;

    // B: row r = tid&127, float4 slots sgrp*2 + {0,1}
    int br = tid & 127;
    int bs = (tid >> 7) * 2;                       // slot pair base (0 or 2)
    const float* bsrc = &g_wsp[br * ASTRIDE + bs * 4];
    float* aSm = &sbuf[0][p * ASTRIDE + kb];
    float* bSm = &sbuf[0][BUFF + br * ASTRIDE + bs * 4];

    uint32_t sb0 = smem_u32(sbuf);

    // ldmatrix lane offsets (validated round 10)
    int mR = lane >> 3, rr = lane & 7;
    uint32_t offA[2], offB[4];
#pragma unroll
    for (int mi = 0; mi < 2; mi++)
        offA[mi] = (((wm * 32 + mi * 16 + (mR & 1) * 8 + rr) * ASTRIDE + (mR >> 1) * 4) << 2);
#pragma unroll
    for (int pr = 0; pr < 4; pr++)
        offB[pr] = (BUFF << 2) + (((wn * 64 + pr * 16 + (mR >> 1) * 8 + rr) * ASTRIDE + (mR & 1) * 4) << 2);

    float acc[2][8][4];
#pragma unroll
    for (int mi = 0; mi < 2; mi++)
#pragma unroll
        for (int ni = 0; ni < 8; ni++)
#pragma unroll
            for (int c = 0; c < 4; c++) acc[mi][ni][c] = 0.f;

    float pa[8];
    float4 pb0, pb1;
    __syncthreads();   // tables ready

    // prologue: chunk 0 -> regs -> stage 0
#pragma unroll
    for (int i = 0; i < 8; i++) pa[i] = valid ? base[skoff[kb + i]] : 0.f;
    pb0 = *(const float4*)(bsrc);
    pb1 = *(const float4*)(bsrc + 4);
    *(float4*)(aSm)     = make_float4(pa[0], pa[1], pa[2], pa[3]);
    *(float4*)(aSm + 4) = make_float4(pa[4], pa[5], pa[6], pa[7]);
    *(float4*)(bSm)     = pb0;
    *(float4*)(bSm + 4) = pb1;

    const uint32_t stageF = 2 * BUFF;   // floats per stage
    for (int ch = 0; ch < NCHUNK; ch++) {
        __syncthreads();               // stage ch&1 ready for all; prev reads done
        if (ch + 1 < NCHUNK) {
            int kg0 = (ch + 1) * KC;
#pragma unroll
            for (int i = 0; i < 8; i++) pa[i] = valid ? base[skoff[kg0 + kb + i]] : 0.f;
            const float* bs2 = bsrc + (ch + 1) * BUFF;
            pb0 = *(const float4*)(bs2);
            pb1 = *(const float4*)(bs2 + 4);
        }

        uint32_t st = (ch & 1) * (stageF << 2);
#pragma unroll
        for (int ks = 0; ks < 2; ks++) {
            uint32_t kofs = st + ks * 32;
            uint32_t a[2][4], b[4][4];
#pragma unroll
            for (int mi = 0; mi < 2; mi++) ldsm_x4(a[mi], sb0 + offA[mi] + kofs);
#pragma unroll
            for (int pr = 0; pr < 4; pr++) ldsm_x4(b[pr], sb0 + offB[pr] + kofs);
#pragma unroll
            for (int mi = 0; mi < 2; mi++)
#pragma unroll
                for (int pr = 0; pr < 4; pr++) {
                    mma_tf32(acc[mi][pr * 2 + 0], a[mi], &b[pr][0]);
                    mma_tf32(acc[mi][pr * 2 + 1], a[mi], &b[pr][2]);
                }
        }

        if (ch + 1 < NCHUNK) {
            float* dA = aSm + ((ch + 1) & 1) * stageF;
            float* dB = bSm + ((ch + 1) & 1) * stageF;
            *(float4*)(dA)     = make_float4(pa[0], pa[1], pa[2], pa[3]);
            *(float4*)(dA + 4) = make_float4(pa[4], pa[5], pa[6], pa[7]);
            *(float4*)(dB)     = pb0;
            *(float4*)(dB + 4) = pb1;
        }
    }
    __syncthreads();   // all MMAs done before epilogue overlays sbuf[0]

    // ---------------- epilogue: 4 column passes of 32 cols ----------------
    float* sm = sbuf[0];   // overlay [128][33] = 4224 floats <= 2*BUFF = 5120
    for (int q = 0; q < 4; q++) {
        if ((q >> 1) == wn) {
            int ni0 = (q & 1) * 4;
#pragma unroll
            for (int mi = 0; mi < 2; mi++) {
#pragma unroll
                for (int nj = 0; nj < 4; nj++) {
                    int ni = ni0 + nj;
                    int colg = wn * 64 + ni * 8 + 2 * tg;
                    int colp = (colg - q * 32);
                    int r0 = wm * 32 + mi * 16 + gq;
#pragma unroll
                    for (int cc = 0; cc < 2; cc++) {
                        float v0 = acc[mi][ni][cc] + sbias[colg + cc];
                        v0 = (v0 >= 0.f) ? v0 : 0.2f * v0;
                        float v2 = acc[mi][ni][2 + cc] + sbias[colg + cc];
                        v2 = (v2 >= 0.f) ? v2 : 0.2f * v2;
                        sm[r0 * 33 + colp + cc] = v0;
                        sm[(r0 + 8) * 33 + colp + cc] = v2;
                    }
                }
            }
        }
        __syncthreads();
        if (tid < 128) {
            int ccol = tid & 31;
            int myreg = tid >> 5;
            float mx = -INFINITY;
            for (int row = 0; row < 128; row++) {
                float v = sm[row * 33 + ccol];
                mx = (srowreg[row] == (unsigned char)myreg) ? fmaxf(mx, v) : mx;
            }
            g_partial[((img * MT + mt) * 4 + myreg) * 128 + q * 32 + ccol] = mx;
        }
        __syncthreads();
    }
}

// ---------------- reduce conv-tile partials -> g_pool_vis ----------------
__global__ void vis_reduce_kernel() {
    int img = blockIdx.x;
    int o = threadIdx.x;    // 512
    int r = o >> 7;
    int col = o & 127;
    float m = -INFINITY;
    for (int mt = 0; mt < MT; mt++)
        m = fmaxf(m, g_partial[((img * MT + mt) * 4 + r) * 128 + col]);
    g_pool_vis[img * 512 + col * 4 + r] = m;
}

// ---------------- vis score ----------------
__global__ void vis_score_kernel(const float* __restrict__ fcvb, float* __restrict__ out) {
    __shared__ float xs[512];
    int b = blockIdx.x, tid = threadIdx.x;
    for (int i = tid; i < 512; i += 256) xs[i] = g_pool_vis[b * 512 + i];
    __syncthreads();
    float acc = fcvb[tid];
    for (int j = 0; j < 512; j++) acc += xs[j] * g_fcvT[j * OUTD + tid];
    out[b * OUTD + tid] = acc;
}

// ---------------- topo score ----------------
__global__ void topo_score_kernel(const float* __restrict__ fctb, float* __restrict__ out) {
    __shared__ float xs[128];
    int b = blockIdx.x, tid = threadIdx.x;
    if (tid < 128) {
        float m = g_topo_part[(b * 4 + 0) * 128 + tid];
        m = fmaxf(m, g_topo_part[(b * 4 + 1) * 128 + tid]);
        m = fmaxf(m, g_topo_part[(b * 4 + 2) * 128 + tid]);
        m = fmaxf(m, g_topo_part[(b * 4 + 3) * 128 + tid]);
        xs[tid] = m;
    }
    __syncthreads();
    float acc = fctb[tid];
    for (int j = 0; j < 128; j++) acc += xs[j] * g_fctT[j * OUTD + tid];
    out[BBATCH * OUTD + b * OUTD + tid] = acc;
}

// ---------------- launch (conv placed 4th: ncu -s5-c1 lands there) ----------------
extern "C" void kernel_launch(void* const* d_in, const int* in_sizes, int n_in,
                              void* d_out, int out_size) {
    const float* vis    = (const float*)d_in[0];
    const float* topo   = (const float*)d_in[1];
    const int*   ei     = (const int*)d_in[2];
    const int*   batch  = (const int*)d_in[3];
    const float* conv_w = (const float*)d_in[4];
    const float* conv_b = (const float*)d_in[5];
    const float* conv_u = (const float*)d_in[6];
    const float* fcv_w  = (const float*)d_in[7];
    const float* fcv_b  = (const float*)d_in[8];
    const float* fcv_u  = (const float*)d_in[9];
    const float* gcn_w  = (const float*)d_in[10];
    const float* gcn_b  = (const float*)d_in[11];
    const float* fct_w  = (const float*)d_in[12];
    const float* fct_b  = (const float*)d_in[13];
    const float* fct_u  = (const float*)d_in[14];
    float*       out    = (float*)d_out;

    // 1..3
    sigma_kernel<<<1, 256>>>(conv_w, conv_u, 128, 1152, 0);
    scale_w<<<(128 * 1152 + 255) / 256, 256>>>(conv_w);
    init_kernel<<<(NN * DD + 255) / 256, 256>>>();
    // 4: conv (profiled slot)
    conv_mma_kernel<<<BBATCH * MT, 256>>>(vis, conv_b);

    // topo head
    deg_kernel<<<(NE + 255) / 256, 256>>>(ei);
    dis_kernel<<<(NN + 255) / 256, 256>>>();
    xw_kernel<<<NN / 8, 128>>>(topo, gcn_w);
    scatter_kernel<<<NE / 8, 256>>>(ei);

    // remaining weight prep
    sigma_kernel<<<1, 256>>>(fcv_w, fcv_u, 256, 512, 1);
    sigma_kernel<<<1, 256>>>(fct_w, fct_u, 256, 128, 2);
    transpose_fcv<<<(256 * 512 + 255) / 256, 256>>>(fcv_w);
    transpose_fct<<<(256 * 128 + 255) / 256, 256>>>(fct_w);

    vis_reduce_kernel<<<BBATCH, 512>>>();
    {
        dim3 g(BBATCH, 4);
        topo_pool_kernel<<<g, 128>>>(batch, gcn_b);
    }

    vis_score_kernel<<<BBATCH, 256>>>(fcv_b, out);
    topo_score_kernel<<<BBATCH, 256>>>(fct_b, out);
}

// round 12
// speedup vs baseline: 2.6597x; 1.2982x over previous
#include <cuda_runtime.h>
#include <math.h>
#include <stdint.h>

#define NN 20000
#define NE 640000
#define DD 128
#define OUTD 256
#define BBATCH 64
#define HOUT 62
#define MPI (HOUT*HOUT)   // 3844 pixels per image
#define MT 31             // M-tiles of 128 per image
#define KTOT 1152
#define KC 16             // K chunk
#define NCHUNK (KTOT/KC)  // 72
#define ASTRIDE 20        // floats per A row (80B): conflict-free STS.128 + ldmatrix
#define BUFF (128*ASTRIDE)

// ---------------- scratch ----------------
__device__ __align__(16) float g_acc[8];               // [slot]{ ||v||^2, ||Wv||^2 }
__device__ __align__(16) float g_sv[3 * 1152];         // v = W^T u per slot
__device__ __align__(16) float g_wfrag[KTOT * DD];     // conv W in mma-fragment order, tf32-rna
__device__ __align__(16) float g_fcvT[512 * OUTD];
__device__ __align__(16) float g_fctT[DD * OUTD];
__device__ __align__(16) float g_partial[BBATCH * MT * 4 * DD];
__device__ __align__(16) float g_pool_vis[BBATCH * DD * 4];
__device__ __align__(16) float g_topo_part[BBATCH * 4 * DD];
__device__ __align__(16) float g_deg[NN];
__device__ __align__(16) float g_dis[NN];
__device__ __align__(16) float g_xw[NN * DD];
__device__ __align__(16) float g_h[NN * DD];

__device__ __forceinline__ int clampi(int v, int lo, int hi) {
    return v < lo ? lo : (v > hi ? hi : v);
}
__device__ __forceinline__ uint32_t f2tf32(float f) {
    uint32_t u;
    asm("cvt.rna.tf32.f32 %0, %1;" : "=r"(u) : "f"(f));
    return u;
}
__device__ __forceinline__ uint32_t smem_u32(const void* p) {
    uint32_t a;
    asm("{ .reg .u64 t; cvta.to.shared.u64 t, %1; cvt.u32.u64 %0, t; }" : "=r"(a) : "l"(p));
    return a;
}
__device__ __forceinline__ void mma_tf32(float* d, const uint32_t* a, const uint32_t* b) {
    asm volatile(
        "mma.sync.aligned.m16n8k8.row.col.f32.tf32.tf32.f32 "
        "{%0,%1,%2,%3}, {%4,%5,%6,%7}, {%8,%9}, {%0,%1,%2,%3};"
        : "+f"(d[0]), "+f"(d[1]), "+f"(d[2]), "+f"(d[3])
        : "r"(a[0]), "r"(a[1]), "r"(a[2]), "r"(a[3]), "r"(b[0]), "r"(b[1]));
}
__device__ __forceinline__ void ldsm_x4(uint32_t* r, uint32_t addr) {
    asm volatile("ldmatrix.sync.aligned.m8n8.x4.shared.b16 {%0,%1,%2,%3}, [%4];"
                 : "=r"(r[0]), "=r"(r[1]), "=r"(r[2]), "=r"(r[3]) : "r"(addr));
}
// sigma = s^2/(s+eps) with s = ||Wv||/(||v||+eps); returns 1/sigma
__device__ __forceinline__ float inv_sigma_from(int slot) {
    float vn = sqrtf(g_acc[slot * 2 + 0]);
    float tn = sqrtf(g_acc[slot * 2 + 1]);
    float s = tn / (vn + 1e-12f);
    float sigma = s * s / (s + 1e-12f);
    return 1.0f / sigma;
}

// ---------------- prep: zero scratch ----------------
__global__ void prep_kernel() {
    int idx = blockIdx.x * 256 + threadIdx.x;
    if (idx < NN * DD) g_h[idx] = 0.f;
    if (idx < NN) g_deg[idx] = 1.0f;     // self loop
    if (idx < 8) g_acc[idx] = 0.f;
}

// ---------------- spectral norm: v = W^T u (coalesced), ||v||^2 ----------------
__global__ void sigma_v(const float* __restrict__ W, const float* __restrict__ u,
                        int R, int C, int slot) {
    int j = blockIdx.x * 256 + threadIdx.x;
    if (j >= C) return;
    float t = 0.f;
    for (int i = 0; i < R; i++) t += W[i * C + j] * u[i];
    g_sv[slot * 1152 + j] = t;
    atomicAdd(&g_acc[slot * 2 + 0], t * t);
}

// ---------------- spectral norm: ||W v||^2, warp per row ----------------
__global__ void sigma_t(const float* __restrict__ W, int R, int C, int slot) {
    int warp = threadIdx.x >> 5, lane = threadIdx.x & 31;
    int i = blockIdx.x * 8 + warp;
    if (i >= R) return;
    const float* sv = &g_sv[slot * 1152];
    float t = 0.f;
    for (int j = lane; j < C; j += 32) t += W[i * C + j] * sv[j];
#pragma unroll
    for (int o = 16; o > 0; o >>= 1) t += __shfl_xor_sync(0xFFFFFFFFu, t, o);
    if (lane == 0) atomicAdd(&g_acc[slot * 2 + 1], t * t);
}

// ---------------- conv weights -> mma fragment order (unscaled, tf32-rna) --------
__global__ void wfrag_kernel(const float* __restrict__ src) {
    int idx = blockIdx.x * 256 + threadIdx.x;
    if (idx >= KTOT * DD) return;
    int w = idx & 3;
    int lane = (idx >> 2) & 31;
    int ks = (idx >> 7) & 1;
    int prg = (idx >> 8) & 7;
    int ch = idx >> 11;
    int cout = prg * 16 + ((w >> 1) << 3) + (lane >> 2);
    int k = ch * 16 + ks * 8 + ((w & 1) << 2) + (lane & 3);
    g_wfrag[idx] = __uint_as_float(f2tf32(src[cout * KTOT + k]));
}

// ---------------- fc weight transpose + scale (inline sigma) ----------------
__global__ void transpose_fcv(const float* __restrict__ src) {
    int idx = blockIdx.x * 256 + threadIdx.x;
    if (idx >= 256 * 512) return;
    int r = idx / 512, c = idx - r * 512;
    g_fcvT[c * 256 + r] = src[idx] * inv_sigma_from(1);
}
__global__ void transpose_fct(const float* __restrict__ src) {
    int idx = blockIdx.x * 256 + threadIdx.x;
    if (idx >= 256 * 128) return;
    int r = idx / 128, c = idx - r * 128;
    g_fctT[c * 256 + r] = src[idx] * inv_sigma_from(2);
}

// ---------------- degree + normalization ----------------
__global__ void deg_kernel(const int* __restrict__ ei) {
    int e = blockIdx.x * 256 + threadIdx.x;
    if (e < NE) atomicAdd(&g_deg[clampi(ei[NE + e], 0, NN - 1)], 1.0f);
}
__global__ void dis_kernel() {
    int i = blockIdx.x * 256 + threadIdx.x;
    if (i < NN) g_dis[i] = rsqrtf(g_deg[i]);
}

// ---------------- xw = topo @ gcn_w ----------------
__global__ void xw_kernel(const float* __restrict__ topo, const float* __restrict__ gw) {
    __shared__ float st[8 * 128];
    int n0 = blockIdx.x * 8;
    int tid = threadIdx.x;
#pragma unroll
    for (int i = 0; i < 8; i++) st[i * 128 + tid] = topo[(n0 + i) * 128 + tid];
    __syncthreads();
    float acc[8];
#pragma unroll
    for (int r = 0; r < 8; r++) acc[r] = 0.f;
    for (int k = 0; k < 128; k++) {
        float w = gw[k * 128 + tid];
#pragma unroll
        for (int r = 0; r < 8; r++) acc[r] += st[r * 128 + k] * w;
    }
#pragma unroll
    for (int r = 0; r < 8; r++) g_xw[(n0 + r) * 128 + tid] = acc[r];
}

// ---------------- edge scatter via red.v4 ----------------
__global__ void scatter_kernel(const int* __restrict__ ei) {
    int e = blockIdx.x * 8 + (threadIdx.x >> 5);
    if (e >= NE) return;
    int lane = threadIdx.x & 31;
    int src = clampi(ei[e], 0, NN - 1);
    int dst = clampi(ei[NE + e], 0, NN - 1);
    float nrm = g_dis[src] * g_dis[dst];
    float4 v = *(const float4*)&g_xw[src * 128 + lane * 4];
    asm volatile("red.global.add.v4.f32 [%0], {%1, %2, %3, %4};"
                 :: "l"(&g_h[dst * 128 + lane * 4]),
                    "f"(v.x * nrm), "f"(v.y * nrm), "f"(v.z * nrm), "f"(v.w * nrm)
                 : "memory");
}

// ---------------- topo pool ----------------
__global__ void topo_pool_kernel(const int* __restrict__ batch, const float* __restrict__ gb) {
    int b = blockIdx.x;
    int stripe = blockIdx.y;
    int c = threadIdx.x;

    int lo = 0, hi = NN;
    while (lo < hi) { int mid = (lo + hi) >> 1; if (batch[mid] < b) lo = mid + 1; else hi = mid; }
    int s = lo;
    lo = s; hi = NN;
    while (lo < hi) { int mid = (lo + hi) >> 1; if (batch[mid] < b + 1) lo = mid + 1; else hi = mid; }
    int e = lo;

    float bias = gb[c];
    float m = -INFINITY;
    for (int n = s + stripe; n < e; n += 4) {
        float d = g_dis[n];
        float val = g_h[n * 128 + c] + d * d * g_xw[n * 128 + c] + bias;
        val = (val >= 0.f) ? val : 0.2f * val;
        m = fmaxf(m, val);
    }
    g_topo_part[(b * 4 + stripe) * 128 + c] = m;
}

// ---------------- conv3x3: tf32 mma; A staged (STS.128+ldsm), B direct frag LDG ----
// block 128 pixels x 128 cout; 8 warps 4x2 (warp tile 32x64)
__global__ void __launch_bounds__(256, 2)
conv_mma_kernel(const float* __restrict__ vis) {
    __shared__ __align__(16) float sbuf[2][BUFF];   // A stages only
    __shared__ int skoff[KTOT];
    __shared__ unsigned char srowreg[128];

    int tid = threadIdx.x;
    int warp = tid >> 5, lane = tid & 31;
    int wm = warp & 3;        // rows 32*wm
    int wn = warp >> 2;       // cols 64*wn
    int gq = lane >> 2, tg = lane & 3;

    int img = blockIdx.x / MT;
    int mt = blockIdx.x - img * MT;
    int m0 = mt * 128;

    for (int k = tid; k < KTOT; k += 256) {
        int ci = k / 9, rem = k - ci * 9, ky = rem / 3, kx = rem - ky * 3;
        skoff[k] = ci * 4096 + ky * 64 + kx;
    }
    if (tid < 128) {
        int s = m0 + tid;
        unsigned char r = 4;
        if (s < MPI) {
            int yy = s / HOUT, xx = s - yy * HOUT;
            r = (unsigned char)(((yy >= 31) ? 2 : 0) + ((xx >= 31) ? 1 : 0));
        }
        srowreg[tid] = r;
    }

    // A gather: pixel p = tid&127, k sub-range kb..kb+7
    int p = tid & 127;
    int kb = (tid >> 7) * 8;
    int s = m0 + p;
    bool valid = (s < MPI);
    int y = valid ? (s / HOUT) : 0;
    int x = valid ? (s - y * HOUT) : 0;
    const float* base = vis + (size_t)img * 128 * 4096 + y * 64 + x;
    float* aSm = &sbuf[0][p * ASTRIDE + kb];

    const uint4* wf4 = (const uint4*)g_wfrag;
    int pbase = (wn * 4) * 64 + lane;   // float4 index base for this warp

    uint32_t sb0 = smem_u32(sbuf);
    int mR = lane >> 3, rr = lane & 7;
    uint32_t offA[2];
#pragma unroll
    for (int mi = 0; mi < 2; mi++)
        offA[mi] = (((wm * 32 + mi * 16 + (mR & 1) * 8 + rr) * ASTRIDE + (mR >> 1) * 4) << 2);

    float acc[2][8][4];
#pragma unroll
    for (int mi = 0; mi < 2; mi++)
#pragma unroll
        for (int ni = 0; ni < 8; ni++)
#pragma unroll
            for (int c = 0; c < 4; c++) acc[mi][ni][c] = 0.f;

    float pa[8];
    __syncthreads();   // tables ready

    // prologue: chunk 0 A -> stage 0
#pragma unroll
    for (int i = 0; i < 8; i++) pa[i] = valid ? base[skoff[kb + i]] : 0.f;
    *(float4*)(aSm)     = make_float4(pa[0], pa[1], pa[2], pa[3]);
    *(float4*)(aSm + 4) = make_float4(pa[4], pa[5], pa[6], pa[7]);

    for (int ch = 0; ch < NCHUNK; ch++) {
        __syncthreads();               // A stage ch&1 ready; prior reads done
        if (ch + 1 < NCHUNK) {
            int kg0 = (ch + 1) * KC;
#pragma unroll
            for (int i = 0; i < 8; i++) pa[i] = valid ? base[skoff[kg0 + kb + i]] : 0.f;
        }

        uint32_t st = (ch & 1) * (BUFF << 2);
        int cbase = ch * 512 + pbase;
#pragma unroll
        for (int ks = 0; ks < 2; ks++) {
            uint32_t a[2][4];
            uint4 q[4];
#pragma unroll
            for (int pr = 0; pr < 4; pr++) q[pr] = wf4[cbase + pr * 64 + ks * 32];
#pragma unroll
            for (int mi = 0; mi < 2; mi++) ldsm_x4(a[mi], sb0 + offA[mi] + st + ks * 32);
#pragma unroll
            for (int mi = 0; mi < 2; mi++)
#pragma unroll
                for (int pr = 0; pr < 4; pr++) {
                    mma_tf32(acc[mi][pr * 2 + 0], a[mi], (const uint32_t*)&q[pr]);
                    mma_tf32(acc[mi][pr * 2 + 1], a[mi], ((const uint32_t*)&q[pr]) + 2);
                }
        }

        if (ch + 1 < NCHUNK) {
            float* dA = aSm + ((ch + 1) & 1) * BUFF;
            *(float4*)(dA)     = make_float4(pa[0], pa[1], pa[2], pa[3]);
            *(float4*)(dA + 4) = make_float4(pa[4], pa[5], pa[6], pa[7]);
        }
    }
    __syncthreads();   // all MMAs done before epilogue overlays sbuf

    // ---------------- epilogue: raw region max, 4 column passes ----------------
    float* sm = &sbuf[0][0];   // overlay [128][33] = 4224 <= 2*BUFF = 5120
    for (int q = 0; q < 4; q++) {
        if ((q >> 1) == wn) {
            int ni0 = (q & 1) * 4;
#pragma unroll
            for (int mi = 0; mi < 2; mi++) {
#pragma unroll
                for (int nj = 0; nj < 4; nj++) {
                    int ni = ni0 + nj;
                    int colg = wn * 64 + ni * 8 + 2 * tg;
                    int colp = (colg - q * 32);
                    int r0 = wm * 32 + mi * 16 + gq;
#pragma unroll
                    for (int cc = 0; cc < 2; cc++) {
                        sm[r0 * 33 + colp + cc] = acc[mi][ni][cc];
                        sm[(r0 + 8) * 33 + colp + cc] = acc[mi][ni][2 + cc];
                    }
                }
            }
        }
        __syncthreads();
        if (tid < 128) {
            int ccol = tid & 31;
            int myreg = tid >> 5;
            float mx = -INFINITY;
            for (int row = 0; row < 128; row++) {
                float v = sm[row * 33 + ccol];
                mx = (srowreg[row] == (unsigned char)myreg) ? fmaxf(mx, v) : mx;
            }
            g_partial[((img * MT + mt) * 4 + myreg) * 128 + q * 32 + ccol] = mx;
        }
        __syncthreads();
    }
}

// ---------------- reduce partials; apply 1/sigma, bias, leaky ----------------
__global__ void vis_reduce_kernel(const float* __restrict__ cb) {
    int img = blockIdx.x;
    int o = threadIdx.x;    // 512
    int r = o >> 7;
    int col = o & 127;
    float m = -INFINITY;
    for (int mt = 0; mt < MT; mt++)
        m = fmaxf(m, g_partial[((img * MT + mt) * 4 + r) * 128 + col]);
    float v = m * inv_sigma_from(0) + cb[col];
    v = (v >= 0.f) ? v : 0.2f * v;
    g_pool_vis[img * 512 + col * 4 + r] = v;
}

// ---------------- vis score ----------------
__global__ void vis_score_kernel(const float* __restrict__ fcvb, float* __restrict__ out) {
    __shared__ float xs[512];
    int b = blockIdx.x, tid = threadIdx.x;
    for (int i = tid; i < 512; i += 256) xs[i] = g_pool_vis[b * 512 + i];
    __syncthreads();
    float acc = fcvb[tid];
    for (int j = 0; j < 512; j++) acc += xs[j] * g_fcvT[j * OUTD + tid];
    out[b * OUTD + tid] = acc;
}

// ---------------- topo score ----------------
__global__ void topo_score_kernel(const float* __restrict__ fctb, float* __restrict__ out) {
    __shared__ float xs[128];
    int b = blockIdx.x, tid = threadIdx.x;
    if (tid < 128) {
        float m = g_topo_part[(b * 4 + 0) * 128 + tid];
        m = fmaxf(m, g_topo_part[(b * 4 + 1) * 128 + tid]);
        m = fmaxf(m, g_topo_part[(b * 4 + 2) * 128 + tid]);
        m = fmaxf(m, g_topo_part[(b * 4 + 3) * 128 + tid]);
        xs[tid] = m;
    }
    __syncthreads();
    float acc = fctb[tid];
    for (int j = 0; j < 128; j++) acc += xs[j] * g_fctT[j * OUTD + tid];
    out[BBATCH * OUTD + b * OUTD + tid] = acc;
}

// ---------------- launch (conv 4th: ncu lands there) ----------------
extern "C" void kernel_launch(void* const* d_in, const int* in_sizes, int n_in,
                              void* d_out, int out_size) {
    const float* vis    = (const float*)d_in[0];
    const float* topo   = (const float*)d_in[1];
    const int*   ei     = (const int*)d_in[2];
    const int*   batch  = (const int*)d_in[3];
    const float* conv_w = (const float*)d_in[4];
    const float* conv_b = (const float*)d_in[5];
    const float* conv_u = (const float*)d_in[6];
    const float* fcv_w  = (const float*)d_in[7];
    const float* fcv_b  = (const float*)d_in[8];
    const float* fcv_u  = (const float*)d_in[9];
    const float* gcn_w  = (const float*)d_in[10];
    const float* gcn_b  = (const float*)d_in[11];
    const float* fct_w  = (const float*)d_in[12];
    const float* fct_b  = (const float*)d_in[13];
    const float* fct_u  = (const float*)d_in[14];
    float*       out    = (float*)d_out;

    // 1..3
    prep_kernel<<<(NN * DD + 255) / 256, 256>>>();
    wfrag_kernel<<<(KTOT * DD + 255) / 256, 256>>>(conv_w);
    sigma_v<<<(1152 + 255) / 256, 256>>>(conv_w, conv_u, 128, 1152, 0);
    // 4: conv (profiled slot; independent of sigma)
    conv_mma_kernel<<<BBATCH * MT, 256>>>(vis);

    sigma_t<<<(128 + 7) / 8, 256>>>(conv_w, 128, 1152, 0);

    // topo head
    deg_kernel<<<(NE + 255) / 256, 256>>>(ei);
    dis_kernel<<<(NN + 255) / 256, 256>>>();
    xw_kernel<<<NN / 8, 128>>>(topo, gcn_w);
    scatter_kernel<<<NE / 8, 256>>>(ei);

    // fc sigmas + transposes
    sigma_v<<<(512 + 255) / 256, 256>>>(fcv_w, fcv_u, 256, 512, 1);
    sigma_t<<<(256 + 7) / 8, 256>>>(fcv_w, 256, 512, 1);
    sigma_v<<<(128 + 255) / 256, 256>>>(fct_w, fct_u, 256, 128, 2);
    sigma_t<<<(256 + 7) / 8, 256>>>(fct_w, 256, 128, 2);
    transpose_fcv<<<(256 * 512 + 255) / 256, 256>>>(fcv_w);
    transpose_fct<<<(256 * 128 + 255) / 256, 256>>>(fct_w);

    vis_reduce_kernel<<<BBATCH, 512>>>(conv_b);
    {
        dim3 g(BBATCH, 4);
        topo_pool_kernel<<<g, 128>>>(batch, gcn_b);
    }

    vis_score_kernel<<<BBATCH, 256>>>(fcv_b, out);
    topo_score_kernel<<<BBATCH, 256>>>(fct_b, out);
}

// round 13
// speedup vs baseline: 2.8510x; 1.0720x over previous
#include <cuda_runtime.h>
#include <math.h>
#include <stdint.h>

#define NN 20000
#define NE 640000
#define DD 128
#define OUTD 256
#define BBATCH 64
#define HOUT 62
#define MPI (HOUT*HOUT)   // 3844 pixels per image
#define MT 31             // M-tiles of 128 per image
#define KTOT 1152
#define KC 16             // K chunk
#define NCHUNK (KTOT/KC)  // 72
#define ASTRIDE 20        // floats per A row (80B): conflict-free STS.128 + ldmatrix
#define BUFF (128*ASTRIDE)

// ---------------- scratch ----------------
__device__ __align__(16) float g_acc[8];               // [slot]{ ||v||^2, ||Wv||^2 }
__device__ __align__(16) float g_sv[3 * 1152];         // v = W^T u per slot
__device__ __align__(16) float g_wfrag[KTOT * DD];     // conv W in mma-fragment order, tf32-rna
__device__ __align__(16) float g_fcvT[512 * OUTD];
__device__ __align__(16) float g_fctT[DD * OUTD];
__device__ __align__(16) float g_partial[BBATCH * MT * 4 * DD];
__device__ __align__(16) float g_pool_vis[BBATCH * DD * 4];
__device__ __align__(16) float g_topo_part[BBATCH * 4 * DD];
__device__ __align__(16) float g_deg[NN];
__device__ __align__(16) float g_dis[NN];
__device__ __align__(16) float g_xw[NN * DD];
__device__ __align__(16) float g_h[NN * DD];

__device__ __forceinline__ int clampi(int v, int lo, int hi) {
    return v < lo ? lo : (v > hi ? hi : v);
}
__device__ __forceinline__ uint32_t f2tf32(float f) {
    uint32_t u;
    asm("cvt.rna.tf32.f32 %0, %1;" : "=r"(u) : "f"(f));
    return u;
}
__device__ __forceinline__ uint32_t smem_u32(const void* p) {
    uint32_t a;
    asm("{ .reg .u64 t; cvta.to.shared.u64 t, %1; cvt.u32.u64 %0, t; }" : "=r"(a) : "l"(p));
    return a;
}
__device__ __forceinline__ void mma_tf32(float* d, const uint32_t* a, const uint32_t* b) {
    asm volatile(
        "mma.sync.aligned.m16n8k8.row.col.f32.tf32.tf32.f32 "
        "{%0,%1,%2,%3}, {%4,%5,%6,%7}, {%8,%9}, {%0,%1,%2,%3};"
        : "+f"(d[0]), "+f"(d[1]), "+f"(d[2]), "+f"(d[3])
        : "r"(a[0]), "r"(a[1]), "r"(a[2]), "r"(a[3]), "r"(b[0]), "r"(b[1]));
}
__device__ __forceinline__ void ldsm_x4(uint32_t* r, uint32_t addr) {
    asm volatile("ldmatrix.sync.aligned.m8n8.x4.shared.b16 {%0,%1,%2,%3}, [%4];"
                 : "=r"(r[0]), "=r"(r[1]), "=r"(r[2]), "=r"(r[3]) : "r"(addr));
}
__device__ __forceinline__ void cp_async16(uint32_t dst, const void* src) {
    asm volatile("cp.async.cg.shared.global [%0], [%1], 16;"
                 :: "r"(dst), "l"(src) : "memory");
}
// sigma = s^2/(s+eps) with s = ||Wv||/(||v||+eps); returns 1/sigma
__device__ __forceinline__ float inv_sigma_from(int slot) {
    float vn = sqrtf(g_acc[slot * 2 + 0]);
    float tn = sqrtf(g_acc[slot * 2 + 1]);
    float s = tn / (vn + 1e-12f);
    float sigma = s * s / (s + 1e-12f);
    return 1.0f / sigma;
}

// ---------------- prep: zero scratch ----------------
__global__ void prep_kernel() {
    int idx = blockIdx.x * 256 + threadIdx.x;
    if (idx < NN * DD) g_h[idx] = 0.f;
    if (idx < NN) g_deg[idx] = 1.0f;     // self loop
    if (idx < 8) g_acc[idx] = 0.f;
}

// ---------------- spectral norm: v = W^T u (coalesced), ||v||^2 ----------------
__global__ void sigma_v(const float* __restrict__ W, const float* __restrict__ u,
                        int R, int C, int slot) {
    int j = blockIdx.x * 256 + threadIdx.x;
    if (j >= C) return;
    float t = 0.f;
    for (int i = 0; i < R; i++) t += W[i * C + j] * u[i];
    g_sv[slot * 1152 + j] = t;
    atomicAdd(&g_acc[slot * 2 + 0], t * t);
}

// ---------------- spectral norm: ||W v||^2, warp per row ----------------
__global__ void sigma_t(const float* __restrict__ W, int R, int C, int slot) {
    int warp = threadIdx.x >> 5, lane = threadIdx.x & 31;
    int i = blockIdx.x * 8 + warp;
    if (i >= R) return;
    const float* sv = &g_sv[slot * 1152];
    float t = 0.f;
    for (int j = lane; j < C; j += 32) t += W[i * C + j] * sv[j];
#pragma unroll
    for (int o = 16; o > 0; o >>= 1) t += __shfl_xor_sync(0xFFFFFFFFu, t, o);
    if (lane == 0) atomicAdd(&g_acc[slot * 2 + 1], t * t);
}

// ---------------- conv weights -> mma fragment order (unscaled, tf32-rna) --------
__global__ void wfrag_kernel(const float* __restrict__ src) {
    int idx = blockIdx.x * 256 + threadIdx.x;
    if (idx >= KTOT * DD) return;
    int w = idx & 3;
    int lane = (idx >> 2) & 31;
    int ks = (idx >> 7) & 1;
    int prg = (idx >> 8) & 7;
    int ch = idx >> 11;
    int cout = prg * 16 + ((w >> 1) << 3) + (lane >> 2);
    int k = ch * 16 + ks * 8 + ((w & 1) << 2) + (lane & 3);
    g_wfrag[idx] = __uint_as_float(f2tf32(src[cout * KTOT + k]));
}

// ---------------- fc weight transpose + scale (inline sigma) ----------------
__global__ void transpose_fcv(const float* __restrict__ src) {
    int idx = blockIdx.x * 256 + threadIdx.x;
    if (idx >= 256 * 512) return;
    int r = idx / 512, c = idx - r * 512;
    g_fcvT[c * 256 + r] = src[idx] * inv_sigma_from(1);
}
__global__ void transpose_fct(const float* __restrict__ src) {
    int idx = blockIdx.x * 256 + threadIdx.x;
    if (idx >= 256 * 128) return;
    int r = idx / 128, c = idx - r * 128;
    g_fctT[c * 256 + r] = src[idx] * inv_sigma_from(2);
}

// ---------------- degree + normalization ----------------
__global__ void deg_kernel(const int* __restrict__ ei) {
    int e = blockIdx.x * 256 + threadIdx.x;
    if (e < NE) atomicAdd(&g_deg[clampi(ei[NE + e], 0, NN - 1)], 1.0f);
}
__global__ void dis_kernel() {
    int i = blockIdx.x * 256 + threadIdx.x;
    if (i < NN) g_dis[i] = rsqrtf(g_deg[i]);
}

// ---------------- xw = topo @ gcn_w ----------------
__global__ void xw_kernel(const float* __restrict__ topo, const float* __restrict__ gw) {
    __shared__ float st[8 * 128];
    int n0 = blockIdx.x * 8;
    int tid = threadIdx.x;
#pragma unroll
    for (int i = 0; i < 8; i++) st[i * 128 + tid] = topo[(n0 + i) * 128 + tid];
    __syncthreads();
    float acc[8];
#pragma unroll
    for (int r = 0; r < 8; r++) acc[r] = 0.f;
    for (int k = 0; k < 128; k++) {
        float w = gw[k * 128 + tid];
#pragma unroll
        for (int r = 0; r < 8; r++) acc[r] += st[r * 128 + k] * w;
    }
#pragma unroll
    for (int r = 0; r < 8; r++) g_xw[(n0 + r) * 128 + tid] = acc[r];
}

// ---------------- edge scatter via red.v4 ----------------
__global__ void scatter_kernel(const int* __restrict__ ei) {
    int e = blockIdx.x * 8 + (threadIdx.x >> 5);
    if (e >= NE) return;
    int lane = threadIdx.x & 31;
    int src = clampi(ei[e], 0, NN - 1);
    int dst = clampi(ei[NE + e], 0, NN - 1);
    float nrm = g_dis[src] * g_dis[dst];
    float4 v = *(const float4*)&g_xw[src * 128 + lane * 4];
    asm volatile("red.global.add.v4.f32 [%0], {%1, %2, %3, %4};"
                 :: "l"(&g_h[dst * 128 + lane * 4]),
                    "f"(v.x * nrm), "f"(v.y * nrm), "f"(v.z * nrm), "f"(v.w * nrm)
                 : "memory");
}

// ---------------- topo pool ----------------
__global__ void topo_pool_kernel(const int* __restrict__ batch, const float* __restrict__ gb) {
    int b = blockIdx.x;
    int stripe = blockIdx.y;
    int c = threadIdx.x;

    int lo = 0, hi = NN;
    while (lo < hi) { int mid = (lo + hi) >> 1; if (batch[mid] < b) lo = mid + 1; else hi = mid; }
    int s = lo;
    lo = s; hi = NN;
    while (lo < hi) { int mid = (lo + hi) >> 1; if (batch[mid] < b + 1) lo = mid + 1; else hi = mid; }
    int e = lo;

    float bias = gb[c];
    float m = -INFINITY;
    for (int n = s + stripe; n < e; n += 4) {
        float d = g_dis[n];
        float val = g_h[n * 128 + c] + d * d * g_xw[n * 128 + c] + bias;
        val = (val >= 0.f) ? val : 0.2f * val;
        m = fmaxf(m, val);
    }
    g_topo_part[(b * 4 + stripe) * 128 + c] = m;
}

// ---------------- conv3x3: tf32 mma; A staged (STS.128+ldsm), B cp.async->LDS.128 --
// block 128 pixels x 128 cout; 8 warps 4x2 (warp tile 32x64)
__global__ void __launch_bounds__(256, 2)
conv_mma_kernel(const float* __restrict__ vis) {
    __shared__ __align__(16) float sA[2][BUFF];     // 20KB
    __shared__ __align__(16) uint4 sB[2][512];      // 16KB (fragment order, linear)
    __shared__ int skoff[KTOT];
    __shared__ unsigned char srowreg[128];

    int tid = threadIdx.x;
    int warp = tid >> 5, lane = tid & 31;
    int wm = warp & 3;        // rows 32*wm
    int wn = warp >> 2;       // cols 64*wn
    int gq = lane >> 2, tg = lane & 3;

    int img = blockIdx.x / MT;
    int mt = blockIdx.x - img * MT;
    int m0 = mt * 128;

    for (int k = tid; k < KTOT; k += 256) {
        int ci = k / 9, rem = k - ci * 9, ky = rem / 3, kx = rem - ky * 3;
        skoff[k] = ci * 4096 + ky * 64 + kx;
    }
    if (tid < 128) {
        int s = m0 + tid;
        unsigned char r = 4;
        if (s < MPI) {
            int yy = s / HOUT, xx = s - yy * HOUT;
            r = (unsigned char)(((yy >= 31) ? 2 : 0) + ((xx >= 31) ? 1 : 0));
        }
        srowreg[tid] = r;
    }

    // A gather: pixel p = tid&127, k sub-range kb..kb+7
    int p = tid & 127;
    int kb = (tid >> 7) * 8;
    int s = m0 + p;
    bool valid = (s < MPI);
    int y = valid ? (s / HOUT) : 0;
    int x = valid ? (s - y * HOUT) : 0;
    const float* base = vis + (size_t)img * 128 * 4096 + y * 64 + x;
    float* aSm = &sA[0][p * ASTRIDE + kb];

    const uint4* wf4 = (const uint4*)g_wfrag;
    int pbase = wn * 256 + lane;   // uint4 index base within a chunk's 512

    uint32_t sa0 = smem_u32(sA);
    uint32_t sbB = smem_u32(sB);
    uint32_t bDst = sbB + tid * 16;                 // this thread's 2 cp.async slots
    const uint32_t bStageBytes = 512 * 16;

    int mR = lane >> 3, rr = lane & 7;
    uint32_t offA[2];
#pragma unroll
    for (int mi = 0; mi < 2; mi++)
        offA[mi] = (((wm * 32 + mi * 16 + (mR & 1) * 8 + rr) * ASTRIDE + (mR >> 1) * 4) << 2);

    float acc[2][8][4];
#pragma unroll
    for (int mi = 0; mi < 2; mi++)
#pragma unroll
        for (int ni = 0; ni < 8; ni++)
#pragma unroll
            for (int c = 0; c < 4; c++) acc[mi][ni][c] = 0.f;

    float pa[8];
    __syncthreads();   // tables ready

    // prologue: B chunk0 via cp.async; A chunk0 via regs -> stage 0
    cp_async16(bDst, wf4 + tid);
    cp_async16(bDst + 4096, wf4 + tid + 256);
    asm volatile("cp.async.commit_group;" ::: "memory");
#pragma unroll
    for (int i = 0; i < 8; i++) pa[i] = valid ? base[skoff[kb + i]] : 0.f;
    *(float4*)(aSm)     = make_float4(pa[0], pa[1], pa[2], pa[3]);
    *(float4*)(aSm + 4) = make_float4(pa[4], pa[5], pa[6], pa[7]);

    for (int ch = 0; ch < NCHUNK; ch++) {
        asm volatile("cp.async.wait_group 0;" ::: "memory");   // B(ch) landed (own copies)
        __syncthreads();   // everyone's A(ch)+B(ch) visible; stage (ch+1)&1 free

        if (ch + 1 < NCHUNK) {
            // issue B(ch+1) (hidden behind this chunk's MMAs)
            uint32_t bd = bDst + ((ch + 1) & 1) * bStageBytes;
            const uint4* ws = wf4 + (ch + 1) * 512 + tid;
            cp_async16(bd, ws);
            cp_async16(bd + 4096, ws + 256);
            asm volatile("cp.async.commit_group;" ::: "memory");
            // prefetch A(ch+1) into regs
            int kg0 = (ch + 1) * KC;
#pragma unroll
            for (int i = 0; i < 8; i++) pa[i] = valid ? base[skoff[kg0 + kb + i]] : 0.f;
        }

        uint32_t stA = (ch & 1) * (BUFF << 2);
        const uint4* sBc = sB[ch & 1];
#pragma unroll
        for (int ks = 0; ks < 2; ks++) {
            uint32_t a[2][4];
            uint4 q[4];
#pragma unroll
            for (int pr = 0; pr < 4; pr++) q[pr] = sBc[pbase + pr * 64 + ks * 32];
#pragma unroll
            for (int mi = 0; mi < 2; mi++) ldsm_x4(a[mi], sa0 + offA[mi] + stA + ks * 32);
#pragma unroll
            for (int mi = 0; mi < 2; mi++)
#pragma unroll
                for (int pr = 0; pr < 4; pr++) {
                    mma_tf32(acc[mi][pr * 2 + 0], a[mi], (const uint32_t*)&q[pr]);
                    mma_tf32(acc[mi][pr * 2 + 1], a[mi], ((const uint32_t*)&q[pr]) + 2);
                }
        }

        if (ch + 1 < NCHUNK) {
            float* dA = aSm + ((ch + 1) & 1) * BUFF;
            *(float4*)(dA)     = make_float4(pa[0], pa[1], pa[2], pa[3]);
            *(float4*)(dA + 4) = make_float4(pa[4], pa[5], pa[6], pa[7]);
        }
    }
    __syncthreads();   // all MMAs done before epilogue overlays sA

    // ---------------- epilogue: raw region max, 4 column passes ----------------
    float* sm = &sA[0][0];   // overlay [128][33] = 4224 <= 2*BUFF = 5120
    for (int q = 0; q < 4; q++) {
        if ((q >> 1) == wn) {
            int ni0 = (q & 1) * 4;
#pragma unroll
            for (int mi = 0; mi < 2; mi++) {
#pragma unroll
                for (int nj = 0; nj < 4; nj++) {
                    int ni = ni0 + nj;
                    int colg = wn * 64 + ni * 8 + 2 * tg;
                    int colp = (colg - q * 32);
                    int r0 = wm * 32 + mi * 16 + gq;
#pragma unroll
                    for (int cc = 0; cc < 2; cc++) {
                        sm[r0 * 33 + colp + cc] = acc[mi][ni][cc];
                        sm[(r0 + 8) * 33 + colp + cc] = acc[mi][ni][2 + cc];
                    }
                }
            }
        }
        __syncthreads();
        if (tid < 128) {
            int ccol = tid & 31;
            int myreg = tid >> 5;
            float mx = -INFINITY;
            for (int row = 0; row < 128; row++) {
                float v = sm[row * 33 + ccol];
                mx = (srowreg[row] == (unsigned char)myreg) ? fmaxf(mx, v) : mx;
            }
            g_partial[((img * MT + mt) * 4 + myreg) * 128 + q * 32 + ccol] = mx;
        }
        __syncthreads();
    }
}

// ---------------- reduce partials; apply 1/sigma, bias, leaky ----------------
__global__ void vis_reduce_kernel(const float* __restrict__ cb) {
    int img = blockIdx.x;
    int o = threadIdx.x;    // 512
    int r = o >> 7;
    int col = o & 127;
    float m = -INFINITY;
    for (int mt = 0; mt < MT; mt++)
        m = fmaxf(m, g_partial[((img * MT + mt) * 4 + r) * 128 + col]);
    float v = m * inv_sigma_from(0) + cb[col];
    v = (v >= 0.f) ? v : 0.2f * v;
    g_pool_vis[img * 512 + col * 4 + r] = v;
}

// ---------------- vis score ----------------
__global__ void vis_score_kernel(const float* __restrict__ fcvb, float* __restrict__ out) {
    __shared__ float xs[512];
    int b = blockIdx.x, tid = threadIdx.x;
    for (int i = tid; i < 512; i += 256) xs[i] = g_pool_vis[b * 512 + i];
    __syncthreads();
    float acc = fcvb[tid];
    for (int j = 0; j < 512; j++) acc += xs[j] * g_fcvT[j * OUTD + tid];
    out[b * OUTD + tid] = acc;
}

// ---------------- topo score ----------------
__global__ void topo_score_kernel(const float* __restrict__ fctb, float* __restrict__ out) {
    __shared__ float xs[128];
    int b = blockIdx.x, tid = threadIdx.x;
    if (tid < 128) {
        float m = g_topo_part[(b * 4 + 0) * 128 + tid];
        m = fmaxf(m, g_topo_part[(b * 4 + 1) * 128 + tid]);
        m = fmaxf(m, g_topo_part[(b * 4 + 2) * 128 + tid]);
        m = fmaxf(m, g_topo_part[(b * 4 + 3) * 128 + tid]);
        xs[tid] = m;
    }
    __syncthreads();
    float acc = fctb[tid];
    for (int j = 0; j < 128; j++) acc += xs[j] * g_fctT[j * OUTD + tid];
    out[BBATCH * OUTD + b * OUTD + tid] = acc;
}

// ---------------- launch (conv 4th: ncu lands there) ----------------
extern "C" void kernel_launch(void* const* d_in, const int* in_sizes, int n_in,
                              void* d_out, int out_size) {
    const float* vis    = (const float*)d_in[0];
    const float* topo   = (const float*)d_in[1];
    const int*   ei     = (const int*)d_in[2];
    const int*   batch  = (const int*)d_in[3];
    const float* conv_w = (const float*)d_in[4];
    const float* conv_b = (const float*)d_in[5];
    const float* conv_u = (const float*)d_in[6];
    const float* fcv_w  = (const float*)d_in[7];
    const float* fcv_b  = (const float*)d_in[8];
    const float* fcv_u  = (const float*)d_in[9];
    const float* gcn_w  = (const float*)d_in[10];
    const float* gcn_b  = (const float*)d_in[11];
    const float* fct_w  = (const float*)d_in[12];
    const float* fct_b  = (const float*)d_in[13];
    const float* fct_u  = (const float*)d_in[14];
    float*       out    = (float*)d_out;

    // 1..3
    prep_kernel<<<(NN * DD + 255) / 256, 256>>>();
    wfrag_kernel<<<(KTOT * DD + 255) / 256, 256>>>(conv_w);
    sigma_v<<<(1152 + 255) / 256, 256>>>(conv_w, conv_u, 128, 1152, 0);
    // 4: conv (profiled slot; independent of sigma)
    conv_mma_kernel<<<BBATCH * MT, 256>>>(vis);

    sigma_t<<<(128 + 7) / 8, 256>>>(conv_w, 128, 1152, 0);

    // topo head
    deg_kernel<<<(NE + 255) / 256, 256>>>(ei);
    dis_kernel<<<(NN + 255) / 256, 256>>>();
    xw_kernel<<<NN / 8, 128>>>(topo, gcn_w);
    scatter_kernel<<<NE / 8, 256>>>(ei);

    // fc sigmas + transposes
    sigma_v<<<(512 + 255) / 256, 256>>>(fcv_w, fcv_u, 256, 512, 1);
    sigma_t<<<(256 + 7) / 8, 256>>>(fcv_w, 256, 512, 1);
    sigma_v<<<(128 + 255) / 256, 256>>>(fct_w, fct_u, 256, 128, 2);
    sigma_t<<<(256 + 7) / 8, 256>>>(fct_w, 256, 128, 2);
    transpose_fcv<<<(256 * 512 + 255) / 256, 256>>>(fcv_w);
    transpose_fct<<<(256 * 128 + 255) / 256, 256>>>(fct_w);

    vis_reduce_kernel<<<BBATCH, 512>>>(conv_b);
    {
        dim3 g(BBATCH, 4);
        topo_pool_kernel<<<g, 128>>>(batch, gcn_b);
    }

    vis_score_kernel<<<BBATCH, 256>>>(fcv_b, out);
    topo_score_kernel<<<BBATCH, 256>>>(fct_b, out);
}